// round 14
// baseline (speedup 1.0000x reference)
#include <cuda_runtime.h>
#include <cuda_fp16.h>
#include <cstdint>
#include <cstddef>

// 2-layer LSTM, T=1024, B=16, I=H=1024.
// R13 base: persistent per-layer kernels; 256 thr; register weights;
// parity-buffered cp.async x staging; x-GEMM split around targeted poll;
// h direct from L2; transposed reduce (LDS.128); early flag release.
// R14 delta: hot poll (no nanosleep) + x-GEMM split 2/6 to cover h-LDG.
#define T_   1024
#define B_   16
#define H_   1024
#define NCTA 128
#define NTHR 256
#define WFRAG_L (NCTA*128*4*32*2)     // u32 per layer = 4,194,304
#define XFRAG_T 8192                  // u32 per timestep A-frag (32 KB)
#define HFRAG_SZ XFRAG_T
#define RED_STRIDE 576                // 16 rows * 36 floats per warp
#define SMEM_BYTES (2*8192*4 + 8*RED_STRIDE*4)   // 83968 B

__device__ __align__(16) uint32_t g_wfrag[2][WFRAG_L];
__device__ __align__(16) uint32_t g_xfrag0[(size_t)T_*XFRAG_T];
__device__ __align__(16) uint32_t g_xfrag1[(size_t)T_*XFRAG_T];
__device__ __align__(16) uint32_t g_hfrag[2*HFRAG_SZ];
__device__ __align__(16) unsigned g_flags[NCTA];

// ---------------------------------------------------------------------------
__global__ void k_reset() {
    int i = blockIdx.x * blockDim.x + threadIdx.x;
    if (i < 2*HFRAG_SZ) g_hfrag[i] = 0u;
    if (i < NCTA) g_flags[i] = 0u;
}

// B-frag layout for [Wih;Whh]: idx = (((c*128+kk)*4+nt)*32+lane)*2+p
// lane=4g+tq ; W row = nt*H + c*8 + g ; k = (kk&63)*16 + 2tq + 8p + {0,1}
// kk<64 -> Wih, kk>=64 -> Whh
__global__ void k_conv_w(const float* __restrict__ Wih0, const float* __restrict__ Whh0,
                         const float* __restrict__ Wih1, const float* __restrict__ Whh1) {
    int layer = blockIdx.y;
    const float* Wih = layer ? Wih1 : Wih0;
    const float* Whh = layer ? Whh1 : Whh0;
    int stride = gridDim.x * blockDim.x;
    for (int idx = blockIdx.x * blockDim.x + threadIdx.x; idx < WFRAG_L; idx += stride) {
        int p    = idx & 1;
        int lane = (idx >> 1) & 31;
        int nt   = (idx >> 6) & 3;
        int kk   = (idx >> 8) & 127;
        int c    = idx >> 15;
        int g = lane >> 2, tq = lane & 3;
        int row = nt * H_ + c * 8 + g;
        int kl  = (kk & 63) * 16 + tq * 2 + p * 8;
        const float2 v = *reinterpret_cast<const float2*>(
            (kk < 64 ? Wih : Whh) + (size_t)row * H_ + kl);
        __half2 hv = __floats2half2_rn(v.x, v.y);
        g_wfrag[layer][idx] = *reinterpret_cast<uint32_t*>(&hv);
    }
}

// A-frag layout for x: per-t idx = (kk*32+lane)*4 + r ; b = g + 8*(r&1) ;
// k = kk*16 + 2tq + 8*(r>>1) + {0,1}
__global__ void k_conv_x(const float* __restrict__ x) {
    size_t total = (size_t)T_ * XFRAG_T;
    size_t stride = (size_t)gridDim.x * blockDim.x;
    for (size_t idx = (size_t)blockIdx.x * blockDim.x + threadIdx.x; idx < total; idx += stride) {
        int it = (int)(idx >> 13);
        int r8 = (int)(idx & (XFRAG_T - 1));
        int kk   = r8 >> 7;
        int lane = (r8 >> 2) & 31;
        int r    = r8 & 3;
        int g = lane >> 2, tq = lane & 3;
        int b  = g + ((r & 1) << 3);
        int kb = kk * 16 + tq * 2 + ((r >> 1) << 3);
        const float2 v = *reinterpret_cast<const float2*>(
            x + ((size_t)it * B_ + b) * H_ + kb);
        __half2 hv = __floats2half2_rn(v.x, v.y);
        g_xfrag0[idx] = *reinterpret_cast<uint32_t*>(&hv);
    }
}

// ---------------------------------------------------------------------------
__device__ __forceinline__ float tanh_ap(float v) {
    float r;
    asm("tanh.approx.f32 %0, %1;" : "=f"(r) : "f"(v));
    return r;
}
__device__ __forceinline__ float sigmoid_ap(float v) {
    return fmaf(tanh_ap(0.5f * v), 0.5f, 0.5f);
}

__device__ __forceinline__ void cpa16(uint32_t dst, const void* src) {
    asm volatile("cp.async.cg.shared.global [%0], [%1], 16;" :: "r"(dst), "l"(src));
}
#define CP_COMMIT asm volatile("cp.async.commit_group;")
#define CP_WAIT0  asm volatile("cp.async.wait_group 0;")

__device__ __forceinline__ uint4 ldcg4(const uint4* p) {
    uint4 v;
    asm volatile("ld.global.cg.v4.u32 {%0,%1,%2,%3}, [%4];"
                 : "=r"(v.x), "=r"(v.y), "=r"(v.z), "=r"(v.w) : "l"(p));
    return v;
}
__device__ __forceinline__ unsigned ld_acq(const unsigned* p) {
    unsigned v;
    asm volatile("ld.acquire.gpu.global.u32 %0, [%1];" : "=r"(v) : "l"(p));
    return v;
}
__device__ __forceinline__ void st_release_u32(unsigned* p, unsigned v) {
    asm volatile("st.release.gpu.global.u32 [%0], %1;" :: "l"(p), "r"(v) : "memory");
}

__device__ __forceinline__ void mma16816(float* acc, const uint4& a, const uint2& b) {
    asm volatile(
        "mma.sync.aligned.m16n8k16.row.col.f32.f16.f16.f32 "
        "{%0,%1,%2,%3}, {%4,%5,%6,%7}, {%8,%9}, {%0,%1,%2,%3};\n"
        : "+f"(acc[0]), "+f"(acc[1]), "+f"(acc[2]), "+f"(acc[3])
        : "r"(a.x), "r"(a.y), "r"(a.z), "r"(a.w), "r"(b.x), "r"(b.y));
}

__global__ void __launch_bounds__(NTHR, 1)
k_lstm_layer(int layer,
             const float* __restrict__ bih, const float* __restrict__ bhh,
             float* __restrict__ out,          // fp32 [T,B,H] (layer1) or null
             float* __restrict__ nh, float* __restrict__ nc) {
    extern __shared__ uint32_t smem[];
    uint32_t* s_x0  = smem;                    // parity 0 x A-frag
    uint32_t* s_x1  = smem + 8192;             // parity 1 x A-frag
    float*    s_red = (float*)(smem + 16384);  // 8*576 floats, [w][b][u*4+g]

    uint32_t sbase;
    asm("{ .reg .u64 t; cvta.to.shared.u64 t, %1; cvt.u32.u64 %0, t; }"
        : "=r"(sbase) : "l"(smem));

    const uint32_t* xfrag = layer ? g_xfrag1 : g_xfrag0;

    const int tid = threadIdx.x, warp = tid >> 5, lane = tid & 31;
    const int cblk = blockIdx.x;
    const int g = lane >> 2, tq = lane & 3;

    // ---- weights -> registers: warp covers x-kk [warp*8,+8) and h-kk 64+[warp*8,+8)
    uint2 bxr[8][4], bhr[8][4];
    {
        const uint32_t* wf = g_wfrag[layer] + (size_t)cblk * 32768;
        #pragma unroll
        for (int j = 0; j < 8; j++) {
            #pragma unroll
            for (int nt = 0; nt < 4; nt++) {
                int kkx = warp * 8 + j;
                int kkh = 64 + warp * 8 + j;
                bxr[j][nt] = *(const uint2*)&wf[((kkx * 4 + nt) * 32 + lane) * 2];
                bhr[j][nt] = *(const uint2*)&wf[((kkh * 4 + nt) * 32 + lane) * 2];
            }
        }
    }

    // ---- prologue: x[0] -> s_x0 via cp.async
    {
        const uint4* xs = (const uint4*)xfrag;
        #pragma unroll
        for (int i = 0; i < 8; i++) cpa16(sbase + (tid + i*NTHR)*16u, xs + tid + i*NTHR);
        CP_COMMIT; CP_WAIT0;
    }

    // ---- cell-thread state (tid<128): b = tid&15, unit u = cblk*8 + (tid>>4)
    float cc = 0.f, bs0 = 0.f, bs1 = 0.f, bs2 = 0.f, bs3 = 0.f;
    int b = 0, u = 0, h_a32 = 0;
    if (tid < 128) {
        b = tid & 15;
        int lu = tid >> 4;
        u = cblk * 8 + lu;
        bs0 = bih[u]        + bhh[u];
        bs1 = bih[H_ + u]   + bhh[H_ + u];
        bs2 = bih[2*H_ + u] + bhh[2*H_ + u];
        bs3 = bih[3*H_ + u] + bhh[3*H_ + u];
        int ue = u & ~1;
        int kl = ue & 15;
        int tq_ = (kl >> 1) & 3;
        int rr  = (b >> 3) + ((kl >> 3) << 1);
        int ln_ = ((b & 7) << 2) | tq_;
        h_a32 = ((ue >> 4) * 32 + ln_) * 4 + rr;
    }
    // this warp polls producer CTAs [16*warp, 16*warp+16)
    const int myflag = warp * 16 + (lane & 15);
    __syncthreads();

    #pragma unroll 1
    for (int t = 0; t < T_; ++t) {
        const uint32_t* s_x  = (t & 1) ? s_x1 : s_x0;
        const uint32_t  A_XN = sbase + (uint32_t)(((t + 1) & 1) ? 8192*4 : 0);

        // ---- stage x[t+1] into the other parity buffer ----
        if (t + 1 < T_) {
            const uint4* xs = (const uint4*)(xfrag + (size_t)(t + 1) * XFRAG_T);
            #pragma unroll
            for (int i = 0; i < 8; i++) cpa16(A_XN + (tid + i*NTHR)*16u, xs + tid + i*NTHR);
        }
        CP_COMMIT;

        float acc[4][4];
        #pragma unroll
        for (int nt = 0; nt < 4; nt++)
            #pragma unroll
            for (int j = 0; j < 4; j++) acc[nt][j] = 0.f;

        // ---- x-GEMM part 1 (producer-independent, overlaps the wait) ----
        #pragma unroll
        for (int j = 0; j < 2; j++) {
            uint4 a = *(const uint4*)&s_x[((warp * 8 + j) * 32 + lane) * 4];
            #pragma unroll
            for (int nt = 0; nt < 4; nt++) mma16816(acc[nt], a, bxr[j][nt]);
        }

        // ---- hot targeted poll: my 16 producer CTAs done with step t-1 ----
        if (t) {
            const unsigned tgt = (unsigned)t;
            for (;;) {
                unsigned v = ld_acq(&g_flags[myflag]);
                if (__all_sync(0xffffffffu, v >= tgt)) break;
            }
        }

        // ---- issue h A-frag LDGs; latency hidden by x-GEMM part 2 ----
        uint4 ah[8];
        {
            const uint4* ha = (const uint4*)(g_hfrag + (size_t)(t & 1) * HFRAG_SZ);
            #pragma unroll
            for (int j = 0; j < 8; j++)
                ah[j] = ldcg4(ha + ((warp * 8 + j) * 32 + lane));
        }

        // ---- x-GEMM part 2 (6 kk -> ~180 cyc of h-LDG cover) ----
        #pragma unroll
        for (int j = 2; j < 8; j++) {
            uint4 a = *(const uint4*)&s_x[((warp * 8 + j) * 32 + lane) * 4];
            #pragma unroll
            for (int nt = 0; nt < 4; nt++) mma16816(acc[nt], a, bxr[j][nt]);
        }

        // ---- h-GEMM ----
        #pragma unroll
        for (int j = 0; j < 8; j++) {
            #pragma unroll
            for (int nt = 0; nt < 4; nt++) mma16816(acc[nt], ah[j], bhr[j][nt]);
        }

        // ---- partials -> s_red[warp][b][u*4 + gate] (transposed layout) ----
        {
            float* rp = s_red + warp * RED_STRIDE;
            #pragma unroll
            for (int nt = 0; nt < 4; nt++) {
                int c0 = (tq * 2) * 4 + nt;
                int c1 = (tq * 2 + 1) * 4 + nt;
                rp[g * 36 + c0]       = acc[nt][0];
                rp[g * 36 + c1]       = acc[nt][1];
                rp[(g + 8) * 36 + c0] = acc[nt][2];
                rp[(g + 8) * 36 + c1] = acc[nt][3];
            }
        }
        __syncthreads();                       // red visible to cell warps

        // ---- cell update (warps 0-3); others idle at the bottom sync ----
        if (tid < 128) {
            int lu = tid >> 4;
            float gi = bs0, gf = bs1, gg = bs2, go = bs3;
            const float* rb = s_red + b * 36 + lu * 4;   // 16B-aligned
            #pragma unroll
            for (int w = 0; w < 8; w++) {
                float4 v = *(const float4*)&rb[w * RED_STRIDE];
                gi += v.x;
                gf += v.y;
                gg += v.z;
                go += v.w;
            }
            float fi = sigmoid_ap(gi);
            float ff = sigmoid_ap(gf);
            float fg = tanh_ap(gg);
            float fo = sigmoid_ap(go);
            cc = ff * cc + fi * fg;
            float hv = fo * tanh_ap(cc);

            unsigned us = (unsigned)__half_as_ushort(__float2half_rn(hv));
            unsigned other = __shfl_xor_sync(0xffffffffu, us, 16);
            uint32_t packed = us | (other << 16);
            if (lane < 16)                     // pack (even u | odd u)
                g_hfrag[(size_t)((t + 1) & 1) * HFRAG_SZ + h_a32] = packed;

            // early publish: h stores HB-ordered by named bar, then release
            asm volatile("bar.sync 1, 128;" ::: "memory");
            if (tid == 0)
                st_release_u32(&g_flags[cblk], (unsigned)(t + 1));

            // off-critical-path stores
            if (layer == 0 && lane < 16)
                g_xfrag1[(size_t)t * XFRAG_T + h_a32] = packed;
            if (layer == 1)
                out[((size_t)t * B_ + b) * H_ + u] = hv;
            if (t == T_ - 1 && nh) {
                nh[b * H_ + u] = hv;
                nc[b * H_ + u] = cc;
            }
        }
        CP_WAIT0;                              // own x[t+1] group done
        __syncthreads();                       // no run-ahead past this point
    }
}

// ---------------------------------------------------------------------------
extern "C" void kernel_launch(void* const* d_in, const int* in_sizes, int n_in,
                              void* d_out, int out_size) {
    const float* x    = (const float*)d_in[0];
    const float* Wih0 = (const float*)d_in[1];
    const float* bih0 = (const float*)d_in[2];
    const float* Whh0 = (const float*)d_in[3];
    const float* bhh0 = (const float*)d_in[4];
    const float* Wih1 = (const float*)d_in[5];
    const float* bih1 = (const float*)d_in[6];
    const float* Whh1 = (const float*)d_in[7];
    const float* bhh1 = (const float*)d_in[8];
    float* out = (float*)d_out;

    float* nh = nullptr;
    float* nc = nullptr;
    const size_t out1_sz = (size_t)T_ * B_ * H_;
    if ((size_t)out_size >= out1_sz + 4 * B_ * H_) {
        nh = out + out1_sz;
        nc = nh + 2 * B_ * H_;
    }

    static bool attr_done = false;
    if (!attr_done) {
        cudaFuncSetAttribute(k_lstm_layer,
                             cudaFuncAttributeMaxDynamicSharedMemorySize, SMEM_BYTES);
        attr_done = true;
    }

    dim3 gw(2048, 2);
    k_conv_w<<<gw, 256>>>(Wih0, Whh0, Wih1, Whh1);
    k_conv_x<<<4096, 256>>>(x);

    k_reset<<<128, 256>>>();
    k_lstm_layer<<<NCTA, NTHR, SMEM_BYTES>>>(0, bih0, bhh0, nullptr, nh, nc);
    k_reset<<<128, 256>>>();
    k_lstm_layer<<<NCTA, NTHR, SMEM_BYTES>>>(1, bih1, bhh1, out,
                                             nh ? nh + B_ * H_ : nullptr,
                                             nc ? nc + B_ * H_ : nullptr);
}

// round 15
// speedup vs baseline: 1.0422x; 1.0422x over previous
#include <cuda_runtime.h>
#include <cuda_fp16.h>
#include <cstdint>
#include <cstddef>

// 2-layer LSTM, T=1024, B=16, I=H=1024.
// R13/R14 base: persistent per-layer kernels; 256 thr; register weights;
// parity-buffered cp.async x staging; x-GEMM split around targeted poll;
// h direct from L2; transposed reduce (LDS.128); early flag release.
// R15 delta: 128B-padded flags (no false sharing) + x[t+1] staging moved
// into the cell phase (L2-quiet window).
#define T_   1024
#define B_   16
#define H_   1024
#define NCTA 128
#define NTHR 256
#define FLAG_STRIDE 32                // one flag per 128B line
#define WFRAG_L (NCTA*128*4*32*2)     // u32 per layer = 4,194,304
#define XFRAG_T 8192                  // u32 per timestep A-frag (32 KB)
#define HFRAG_SZ XFRAG_T
#define RED_STRIDE 576                // 16 rows * 36 floats per warp
#define SMEM_BYTES (2*8192*4 + 8*RED_STRIDE*4)   // 83968 B

__device__ __align__(16) uint32_t g_wfrag[2][WFRAG_L];
__device__ __align__(16) uint32_t g_xfrag0[(size_t)T_*XFRAG_T];
__device__ __align__(16) uint32_t g_xfrag1[(size_t)T_*XFRAG_T];
__device__ __align__(16) uint32_t g_hfrag[2*HFRAG_SZ];
__device__ __align__(128) unsigned g_flags[NCTA*FLAG_STRIDE];

// ---------------------------------------------------------------------------
__global__ void k_reset() {
    int i = blockIdx.x * blockDim.x + threadIdx.x;
    if (i < 2*HFRAG_SZ) g_hfrag[i] = 0u;
    if (i < NCTA*FLAG_STRIDE) g_flags[i] = 0u;
}

// B-frag layout for [Wih;Whh]: idx = (((c*128+kk)*4+nt)*32+lane)*2+p
// lane=4g+tq ; W row = nt*H + c*8 + g ; k = (kk&63)*16 + 2tq + 8p + {0,1}
// kk<64 -> Wih, kk>=64 -> Whh
__global__ void k_conv_w(const float* __restrict__ Wih0, const float* __restrict__ Whh0,
                         const float* __restrict__ Wih1, const float* __restrict__ Whh1) {
    int layer = blockIdx.y;
    const float* Wih = layer ? Wih1 : Wih0;
    const float* Whh = layer ? Whh1 : Whh0;
    int stride = gridDim.x * blockDim.x;
    for (int idx = blockIdx.x * blockDim.x + threadIdx.x; idx < WFRAG_L; idx += stride) {
        int p    = idx & 1;
        int lane = (idx >> 1) & 31;
        int nt   = (idx >> 6) & 3;
        int kk   = (idx >> 8) & 127;
        int c    = idx >> 15;
        int g = lane >> 2, tq = lane & 3;
        int row = nt * H_ + c * 8 + g;
        int kl  = (kk & 63) * 16 + tq * 2 + p * 8;
        const float2 v = *reinterpret_cast<const float2*>(
            (kk < 64 ? Wih : Whh) + (size_t)row * H_ + kl);
        __half2 hv = __floats2half2_rn(v.x, v.y);
        g_wfrag[layer][idx] = *reinterpret_cast<uint32_t*>(&hv);
    }
}

// A-frag layout for x: per-t idx = (kk*32+lane)*4 + r ; b = g + 8*(r&1) ;
// k = kk*16 + 2tq + 8*(r>>1) + {0,1}
__global__ void k_conv_x(const float* __restrict__ x) {
    size_t total = (size_t)T_ * XFRAG_T;
    size_t stride = (size_t)gridDim.x * blockDim.x;
    for (size_t idx = (size_t)blockIdx.x * blockDim.x + threadIdx.x; idx < total; idx += stride) {
        int it = (int)(idx >> 13);
        int r8 = (int)(idx & (XFRAG_T - 1));
        int kk   = r8 >> 7;
        int lane = (r8 >> 2) & 31;
        int r    = r8 & 3;
        int g = lane >> 2, tq = lane & 3;
        int b  = g + ((r & 1) << 3);
        int kb = kk * 16 + tq * 2 + ((r >> 1) << 3);
        const float2 v = *reinterpret_cast<const float2*>(
            x + ((size_t)it * B_ + b) * H_ + kb);
        __half2 hv = __floats2half2_rn(v.x, v.y);
        g_xfrag0[idx] = *reinterpret_cast<uint32_t*>(&hv);
    }
}

// ---------------------------------------------------------------------------
__device__ __forceinline__ float tanh_ap(float v) {
    float r;
    asm("tanh.approx.f32 %0, %1;" : "=f"(r) : "f"(v));
    return r;
}
__device__ __forceinline__ float sigmoid_ap(float v) {
    return fmaf(tanh_ap(0.5f * v), 0.5f, 0.5f);
}

__device__ __forceinline__ void cpa16(uint32_t dst, const void* src) {
    asm volatile("cp.async.cg.shared.global [%0], [%1], 16;" :: "r"(dst), "l"(src));
}
#define CP_COMMIT asm volatile("cp.async.commit_group;")
#define CP_WAIT0  asm volatile("cp.async.wait_group 0;")

__device__ __forceinline__ uint4 ldcg4(const uint4* p) {
    uint4 v;
    asm volatile("ld.global.cg.v4.u32 {%0,%1,%2,%3}, [%4];"
                 : "=r"(v.x), "=r"(v.y), "=r"(v.z), "=r"(v.w) : "l"(p));
    return v;
}
__device__ __forceinline__ unsigned ld_acq(const unsigned* p) {
    unsigned v;
    asm volatile("ld.acquire.gpu.global.u32 %0, [%1];" : "=r"(v) : "l"(p));
    return v;
}
__device__ __forceinline__ void st_release_u32(unsigned* p, unsigned v) {
    asm volatile("st.release.gpu.global.u32 [%0], %1;" :: "l"(p), "r"(v) : "memory");
}

__device__ __forceinline__ void mma16816(float* acc, const uint4& a, const uint2& b) {
    asm volatile(
        "mma.sync.aligned.m16n8k16.row.col.f32.f16.f16.f32 "
        "{%0,%1,%2,%3}, {%4,%5,%6,%7}, {%8,%9}, {%0,%1,%2,%3};\n"
        : "+f"(acc[0]), "+f"(acc[1]), "+f"(acc[2]), "+f"(acc[3])
        : "r"(a.x), "r"(a.y), "r"(a.z), "r"(a.w), "r"(b.x), "r"(b.y));
}

__global__ void __launch_bounds__(NTHR, 1)
k_lstm_layer(int layer,
             const float* __restrict__ bih, const float* __restrict__ bhh,
             float* __restrict__ out,          // fp32 [T,B,H] (layer1) or null
             float* __restrict__ nh, float* __restrict__ nc) {
    extern __shared__ uint32_t smem[];
    uint32_t* s_x0  = smem;                    // parity 0 x A-frag
    uint32_t* s_x1  = smem + 8192;             // parity 1 x A-frag
    float*    s_red = (float*)(smem + 16384);  // 8*576 floats, [w][b][u*4+g]

    uint32_t sbase;
    asm("{ .reg .u64 t; cvta.to.shared.u64 t, %1; cvt.u32.u64 %0, t; }"
        : "=r"(sbase) : "l"(smem));

    const uint32_t* xfrag = layer ? g_xfrag1 : g_xfrag0;

    const int tid = threadIdx.x, warp = tid >> 5, lane = tid & 31;
    const int cblk = blockIdx.x;
    const int g = lane >> 2, tq = lane & 3;

    // ---- weights -> registers: warp covers x-kk [warp*8,+8) and h-kk 64+[warp*8,+8)
    uint2 bxr[8][4], bhr[8][4];
    {
        const uint32_t* wf = g_wfrag[layer] + (size_t)cblk * 32768;
        #pragma unroll
        for (int j = 0; j < 8; j++) {
            #pragma unroll
            for (int nt = 0; nt < 4; nt++) {
                int kkx = warp * 8 + j;
                int kkh = 64 + warp * 8 + j;
                bxr[j][nt] = *(const uint2*)&wf[((kkx * 4 + nt) * 32 + lane) * 2];
                bhr[j][nt] = *(const uint2*)&wf[((kkh * 4 + nt) * 32 + lane) * 2];
            }
        }
    }

    // ---- prologue: x[0] -> s_x0 via cp.async
    {
        const uint4* xs = (const uint4*)xfrag;
        #pragma unroll
        for (int i = 0; i < 8; i++) cpa16(sbase + (tid + i*NTHR)*16u, xs + tid + i*NTHR);
        CP_COMMIT; CP_WAIT0;
    }

    // ---- cell-thread state (tid<128): b = tid&15, unit u = cblk*8 + (tid>>4)
    float cc = 0.f, bs0 = 0.f, bs1 = 0.f, bs2 = 0.f, bs3 = 0.f;
    int b = 0, u = 0, h_a32 = 0;
    if (tid < 128) {
        b = tid & 15;
        int lu = tid >> 4;
        u = cblk * 8 + lu;
        bs0 = bih[u]        + bhh[u];
        bs1 = bih[H_ + u]   + bhh[H_ + u];
        bs2 = bih[2*H_ + u] + bhh[2*H_ + u];
        bs3 = bih[3*H_ + u] + bhh[3*H_ + u];
        int ue = u & ~1;
        int kl = ue & 15;
        int tq_ = (kl >> 1) & 3;
        int rr  = (b >> 3) + ((kl >> 3) << 1);
        int ln_ = ((b & 7) << 2) | tq_;
        h_a32 = ((ue >> 4) * 32 + ln_) * 4 + rr;
    }
    // this warp polls producer CTAs [16*warp, 16*warp+16), padded flags
    const int myflag = (warp * 16 + (lane & 15)) * FLAG_STRIDE;
    __syncthreads();

    #pragma unroll 1
    for (int t = 0; t < T_; ++t) {
        const uint32_t* s_x  = (t & 1) ? s_x1 : s_x0;
        const uint32_t  A_XN = sbase + (uint32_t)(((t + 1) & 1) ? 8192*4 : 0);

        float acc[4][4];
        #pragma unroll
        for (int nt = 0; nt < 4; nt++)
            #pragma unroll
            for (int j = 0; j < 4; j++) acc[nt][j] = 0.f;

        // ---- x-GEMM part 1 (producer-independent, overlaps the wait) ----
        #pragma unroll
        for (int j = 0; j < 2; j++) {
            uint4 a = *(const uint4*)&s_x[((warp * 8 + j) * 32 + lane) * 4];
            #pragma unroll
            for (int nt = 0; nt < 4; nt++) mma16816(acc[nt], a, bxr[j][nt]);
        }

        // ---- hot targeted poll: my 16 producer CTAs done with step t-1 ----
        if (t) {
            const unsigned tgt = (unsigned)t;
            for (;;) {
                unsigned v = ld_acq(&g_flags[myflag]);
                if (__all_sync(0xffffffffu, v >= tgt)) break;
            }
        }

        // ---- issue h A-frag LDGs; latency hidden by x-GEMM part 2 ----
        uint4 ah[8];
        {
            const uint4* ha = (const uint4*)(g_hfrag + (size_t)(t & 1) * HFRAG_SZ);
            #pragma unroll
            for (int j = 0; j < 8; j++)
                ah[j] = ldcg4(ha + ((warp * 8 + j) * 32 + lane));
        }

        // ---- x-GEMM part 2 ----
        #pragma unroll
        for (int j = 2; j < 8; j++) {
            uint4 a = *(const uint4*)&s_x[((warp * 8 + j) * 32 + lane) * 4];
            #pragma unroll
            for (int nt = 0; nt < 4; nt++) mma16816(acc[nt], a, bxr[j][nt]);
        }

        // ---- h-GEMM ----
        #pragma unroll
        for (int j = 0; j < 8; j++) {
            #pragma unroll
            for (int nt = 0; nt < 4; nt++) mma16816(acc[nt], ah[j], bhr[j][nt]);
        }

        // ---- partials -> s_red[warp][b][u*4 + gate] (transposed layout) ----
        {
            float* rp = s_red + warp * RED_STRIDE;
            #pragma unroll
            for (int nt = 0; nt < 4; nt++) {
                int c0 = (tq * 2) * 4 + nt;
                int c1 = (tq * 2 + 1) * 4 + nt;
                rp[g * 36 + c0]       = acc[nt][0];
                rp[g * 36 + c1]       = acc[nt][1];
                rp[(g + 8) * 36 + c0] = acc[nt][2];
                rp[(g + 8) * 36 + c1] = acc[nt][3];
            }
        }

        // ---- stage x[t+1] now: its L2 traffic overlaps the cell phase ----
        if (t + 1 < T_) {
            const uint4* xs = (const uint4*)(xfrag + (size_t)(t + 1) * XFRAG_T);
            #pragma unroll
            for (int i = 0; i < 8; i++) cpa16(A_XN + (tid + i*NTHR)*16u, xs + tid + i*NTHR);
        }
        CP_COMMIT;

        __syncthreads();                       // red visible to cell warps

        // ---- cell update (warps 0-3); others idle at the bottom sync ----
        if (tid < 128) {
            int lu = tid >> 4;
            float gi = bs0, gf = bs1, gg = bs2, go = bs3;
            const float* rb = s_red + b * 36 + lu * 4;   // 16B-aligned
            #pragma unroll
            for (int w = 0; w < 8; w++) {
                float4 v = *(const float4*)&rb[w * RED_STRIDE];
                gi += v.x;
                gf += v.y;
                gg += v.z;
                go += v.w;
            }
            float fi = sigmoid_ap(gi);
            float ff = sigmoid_ap(gf);
            float fg = tanh_ap(gg);
            float fo = sigmoid_ap(go);
            cc = ff * cc + fi * fg;
            float hv = fo * tanh_ap(cc);

            unsigned us = (unsigned)__half_as_ushort(__float2half_rn(hv));
            unsigned other = __shfl_xor_sync(0xffffffffu, us, 16);
            uint32_t packed = us | (other << 16);
            if (lane < 16)                     // pack (even u | odd u)
                g_hfrag[(size_t)((t + 1) & 1) * HFRAG_SZ + h_a32] = packed;

            // early publish: h stores HB-ordered by named bar, then release
            asm volatile("bar.sync 1, 128;" ::: "memory");
            if (tid == 0)
                st_release_u32(&g_flags[cblk * FLAG_STRIDE], (unsigned)(t + 1));

            // off-critical-path stores
            if (layer == 0 && lane < 16)
                g_xfrag1[(size_t)t * XFRAG_T + h_a32] = packed;
            if (layer == 1)
                out[((size_t)t * B_ + b) * H_ + u] = hv;
            if (t == T_ - 1 && nh) {
                nh[b * H_ + u] = hv;
                nc[b * H_ + u] = cc;
            }
        }
        CP_WAIT0;                              // own x[t+1] group done
        __syncthreads();                       // no run-ahead past this point
    }
}

// ---------------------------------------------------------------------------
extern "C" void kernel_launch(void* const* d_in, const int* in_sizes, int n_in,
                              void* d_out, int out_size) {
    const float* x    = (const float*)d_in[0];
    const float* Wih0 = (const float*)d_in[1];
    const float* bih0 = (const float*)d_in[2];
    const float* Whh0 = (const float*)d_in[3];
    const float* bhh0 = (const float*)d_in[4];
    const float* Wih1 = (const float*)d_in[5];
    const float* bih1 = (const float*)d_in[6];
    const float* Whh1 = (const float*)d_in[7];
    const float* bhh1 = (const float*)d_in[8];
    float* out = (float*)d_out;

    float* nh = nullptr;
    float* nc = nullptr;
    const size_t out1_sz = (size_t)T_ * B_ * H_;
    if ((size_t)out_size >= out1_sz + 4 * B_ * H_) {
        nh = out + out1_sz;
        nc = nh + 2 * B_ * H_;
    }

    static bool attr_done = false;
    if (!attr_done) {
        cudaFuncSetAttribute(k_lstm_layer,
                             cudaFuncAttributeMaxDynamicSharedMemorySize, SMEM_BYTES);
        attr_done = true;
    }

    dim3 gw(2048, 2);
    k_conv_w<<<gw, 256>>>(Wih0, Whh0, Wih1, Whh1);
    k_conv_x<<<4096, 256>>>(x);

    k_reset<<<128, 256>>>();
    k_lstm_layer<<<NCTA, NTHR, SMEM_BYTES>>>(0, bih0, bhh0, nullptr, nh, nc);
    k_reset<<<128, 256>>>();
    k_lstm_layer<<<NCTA, NTHR, SMEM_BYTES>>>(1, bih1, bhh1, out,
                                             nh ? nh + B_ * H_ : nullptr,
                                             nc ? nc + B_ * H_ : nullptr);
}

// round 16
// speedup vs baseline: 1.3443x; 1.2899x over previous
#include <cuda_runtime.h>
#include <cuda_fp16.h>
#include <cstdint>
#include <cstddef>

// 2-layer LSTM, T=1024, B=16, I=H=1024.
// Merged-v3: ONE persistent kernel, both layers pipelined (interval s = L0
// step s + L1 step s-1) -> 1025 handoffs. L0 weights in SMEM, L1 weights in
// registers, A-frag lifetimes sequenced to avoid R12's spill. L1 input
// A-frag == L0 h A-frag (no xfrag1). Keeps R13-15: transposed reduce,
// padded flags, hot targeted poll, staging in cell window, early release.
#define T_   1024
#define B_   16
#define H_   1024
#define NCTA 128
#define NTHR 256
#define FLAG_STRIDE 32                 // one flag per 128B line
#define WFRAG_L (NCTA*128*4*32*2)      // u32 per layer = 4,194,304
#define XFRAG_T 8192                   // u32 per timestep A-frag (32 KB)
#define HFRAG_SZ XFRAG_T
#define RED_STRIDE 576                 // 16 floats*36 per b-row
// smem u32: s_x[8192] | s_wx0[16384] | s_wh0[16384] | s_red[16*576]f
#define SMEM_U32 (8192 + 16384 + 16384 + 16*RED_STRIDE)
#define SMEM_BYTES (SMEM_U32*4)        // 200704 B

__device__ __align__(16) uint32_t g_wfrag[2][WFRAG_L];
__device__ __align__(16) uint32_t g_xfrag0[(size_t)T_*XFRAG_T];
__device__ __align__(16) uint32_t g_h0f[2*HFRAG_SZ];
__device__ __align__(16) uint32_t g_h1f[2*HFRAG_SZ];
__device__ __align__(128) unsigned g_flags[NCTA*FLAG_STRIDE];

// ---------------------------------------------------------------------------
__global__ void k_reset() {
    int i = blockIdx.x * blockDim.x + threadIdx.x;
    if (i < 2*HFRAG_SZ) { g_h0f[i] = 0u; g_h1f[i] = 0u; }
    if (i < NCTA*FLAG_STRIDE) g_flags[i] = 0u;
}

// B-frag layout for [Wih;Whh]: idx = (((c*128+kk)*4+nt)*32+lane)*2+p
// lane=4g+tq ; W row = nt*H + c*8 + g ; k = (kk&63)*16 + 2tq + 8p + {0,1}
// kk<64 -> Wih, kk>=64 -> Whh
__global__ void k_conv_w(const float* __restrict__ Wih0, const float* __restrict__ Whh0,
                         const float* __restrict__ Wih1, const float* __restrict__ Whh1) {
    int layer = blockIdx.y;
    const float* Wih = layer ? Wih1 : Wih0;
    const float* Whh = layer ? Whh1 : Whh0;
    int stride = gridDim.x * blockDim.x;
    for (int idx = blockIdx.x * blockDim.x + threadIdx.x; idx < WFRAG_L; idx += stride) {
        int p    = idx & 1;
        int lane = (idx >> 1) & 31;
        int nt   = (idx >> 6) & 3;
        int kk   = (idx >> 8) & 127;
        int c    = idx >> 15;
        int g = lane >> 2, tq = lane & 3;
        int row = nt * H_ + c * 8 + g;
        int kl  = (kk & 63) * 16 + tq * 2 + p * 8;
        const float2 v = *reinterpret_cast<const float2*>(
            (kk < 64 ? Wih : Whh) + (size_t)row * H_ + kl);
        __half2 hv = __floats2half2_rn(v.x, v.y);
        g_wfrag[layer][idx] = *reinterpret_cast<uint32_t*>(&hv);
    }
}

// A-frag layout for x: per-t idx = (kk*32+lane)*4 + r ; b = g + 8*(r&1) ;
// k = kk*16 + 2tq + 8*(r>>1) + {0,1}
__global__ void k_conv_x(const float* __restrict__ x) {
    size_t total = (size_t)T_ * XFRAG_T;
    size_t stride = (size_t)gridDim.x * blockDim.x;
    for (size_t idx = (size_t)blockIdx.x * blockDim.x + threadIdx.x; idx < total; idx += stride) {
        int it = (int)(idx >> 13);
        int r8 = (int)(idx & (XFRAG_T - 1));
        int kk   = r8 >> 7;
        int lane = (r8 >> 2) & 31;
        int r    = r8 & 3;
        int g = lane >> 2, tq = lane & 3;
        int b  = g + ((r & 1) << 3);
        int kb = kk * 16 + tq * 2 + ((r >> 1) << 3);
        const float2 v = *reinterpret_cast<const float2*>(
            x + ((size_t)it * B_ + b) * H_ + kb);
        __half2 hv = __floats2half2_rn(v.x, v.y);
        g_xfrag0[idx] = *reinterpret_cast<uint32_t*>(&hv);
    }
}

// ---------------------------------------------------------------------------
__device__ __forceinline__ float tanh_ap(float v) {
    float r;
    asm("tanh.approx.f32 %0, %1;" : "=f"(r) : "f"(v));
    return r;
}
__device__ __forceinline__ float sigmoid_ap(float v) {
    return fmaf(tanh_ap(0.5f * v), 0.5f, 0.5f);
}

__device__ __forceinline__ void cpa16(uint32_t dst, const void* src) {
    asm volatile("cp.async.cg.shared.global [%0], [%1], 16;" :: "r"(dst), "l"(src));
}
#define CP_COMMIT asm volatile("cp.async.commit_group;")
#define CP_WAIT0  asm volatile("cp.async.wait_group 0;")

__device__ __forceinline__ uint4 ldcg4(const uint4* p) {
    uint4 v;
    asm volatile("ld.global.cg.v4.u32 {%0,%1,%2,%3}, [%4];"
                 : "=r"(v.x), "=r"(v.y), "=r"(v.z), "=r"(v.w) : "l"(p));
    return v;
}
__device__ __forceinline__ unsigned ld_acq(const unsigned* p) {
    unsigned v;
    asm volatile("ld.acquire.gpu.global.u32 %0, [%1];" : "=r"(v) : "l"(p));
    return v;
}
__device__ __forceinline__ void st_release_u32(unsigned* p, unsigned v) {
    asm volatile("st.release.gpu.global.u32 [%0], %1;" :: "l"(p), "r"(v) : "memory");
}

__device__ __forceinline__ void mma16816(float* acc, const uint4& a, const uint2& b) {
    asm volatile(
        "mma.sync.aligned.m16n8k16.row.col.f32.f16.f16.f32 "
        "{%0,%1,%2,%3}, {%4,%5,%6,%7}, {%8,%9}, {%0,%1,%2,%3};\n"
        : "+f"(acc[0]), "+f"(acc[1]), "+f"(acc[2]), "+f"(acc[3])
        : "r"(a.x), "r"(a.y), "r"(a.z), "r"(a.w), "r"(b.x), "r"(b.y));
}

__global__ void __launch_bounds__(NTHR, 1)
k_lstm(const float* __restrict__ bih0, const float* __restrict__ bhh0,
       const float* __restrict__ bih1, const float* __restrict__ bhh1,
       float* __restrict__ out, float* __restrict__ nh, float* __restrict__ nc) {
    extern __shared__ uint32_t smem[];
    uint32_t* s_x   = smem;                     // 8192 u32 x A-frag
    uint32_t* s_wx0 = smem + 8192;              // L0 Wih (kk 0..63)
    uint32_t* s_wh0 = smem + 24576;             // L0 Whh (kk 64..127, local 0..63)
    float*    s_red = (float*)(smem + 40960);   // 16 rows * 576 f

    uint32_t sbase;
    asm("{ .reg .u64 t; cvta.to.shared.u64 t, %1; cvt.u32.u64 %0, t; }"
        : "=r"(sbase) : "l"(smem));
    const uint32_t A_X = sbase;
    const uint32_t A_W = sbase + 8192u*4u;

    const int tid = threadIdx.x, warp = tid >> 5, lane = tid & 31;
    const int cblk = blockIdx.x;
    const int g = lane >> 2, tq = lane & 3;

    // ---- L1 weights -> registers: in-kk [8w,8w+8), h1-kk 64+[8w,8w+8)
    uint2 bi1r[8][4], bh1r[8][4];
    {
        const uint32_t* wf1 = g_wfrag[1] + (size_t)cblk * 32768;
        #pragma unroll
        for (int j = 0; j < 8; j++) {
            #pragma unroll
            for (int nt = 0; nt < 4; nt++) {
                int kki = warp * 8 + j;
                int kkh = 64 + warp * 8 + j;
                bi1r[j][nt] = *(const uint2*)&wf1[((kki * 4 + nt) * 32 + lane) * 2];
                bh1r[j][nt] = *(const uint2*)&wf1[((kkh * 4 + nt) * 32 + lane) * 2];
            }
        }
    }

    // ---- prologue: L0 weights (128 KB) + x[0] -> smem via cp.async ----
    {
        const uint4* w0 = (const uint4*)(g_wfrag[0] + (size_t)cblk * 32768);
        #pragma unroll
        for (int i = 0; i < 32; i++)
            cpa16(A_W + (tid + i*NTHR)*16u, w0 + tid + i*NTHR);
        const uint4* xs = (const uint4*)g_xfrag0;
        #pragma unroll
        for (int i = 0; i < 8; i++)
            cpa16(A_X + (tid + i*NTHR)*16u, xs + tid + i*NTHR);
        CP_COMMIT; CP_WAIT0;
    }

    // ---- cell state: cl = layer (warps 0-3 -> L0, 4-7 -> L1) ----
    const int cl = tid >> 7;
    const int wg = tid & 127;
    const int b  = wg & 15;
    const int lu = wg >> 4;
    const int u  = cblk * 8 + lu;
    float cc = 0.f;
    float bs0, bs1, bs2, bs3;
    {
        const float* bi = cl ? bih1 : bih0;
        const float* bh = cl ? bhh1 : bhh0;
        bs0 = bi[u]        + bh[u];
        bs1 = bi[H_ + u]   + bh[H_ + u];
        bs2 = bi[2*H_ + u] + bh[2*H_ + u];
        bs3 = bi[3*H_ + u] + bh[3*H_ + u];
    }
    int h_a32;
    {
        int ue = u & ~1;
        int kl = ue & 15;
        int tq_ = (kl >> 1) & 3;
        int rr  = (b >> 3) + ((kl >> 3) << 1);
        int ln_ = ((b & 7) << 2) | tq_;
        h_a32 = ((ue >> 4) * 32 + ln_) * 4 + rr;
    }
    const int myflag = (warp * 16 + (lane & 15)) * FLAG_STRIDE;
    __syncthreads();

    #pragma unroll 1
    for (int s = 0; s <= T_; ++s) {
        // ---- L0 x-GEMM (pre-poll; A and B from smem) ----
        float acc0[4][4];
        #pragma unroll
        for (int nt = 0; nt < 4; nt++)
            #pragma unroll
            for (int j = 0; j < 4; j++) acc0[nt][j] = 0.f;
        #pragma unroll
        for (int j = 0; j < 8; j++) {
            int kk = warp * 8 + j;
            uint4 a = *(const uint4*)&s_x[(kk * 32 + lane) * 4];
            #pragma unroll
            for (int nt = 0; nt < 4; nt++) {
                uint2 bb = *(const uint2*)&s_wx0[((kk * 4 + nt) * 32 + lane) * 2];
                mma16816(acc0[nt], a, bb);
            }
        }

        // ---- hot targeted poll: producers CTAs [16w,16w+16) done s-1 ----
        if (s) {
            const unsigned tgt = (unsigned)s;
            for (;;) {
                unsigned v = ld_acq(&g_flags[myflag]);
                if (__all_sync(0xffffffffu, v >= tgt)) break;
            }
        }

        // ---- ah0 = h0[s-1] slice (feeds L0h AND L1in) ----
        uint4 ah0[8];
        {
            const uint4* h0p = (const uint4*)(g_h0f + (size_t)(s & 1) * HFRAG_SZ);
            #pragma unroll
            for (int j = 0; j < 8; j++)
                ah0[j] = ldcg4(h0p + ((warp * 8 + j) * 32 + lane));
        }

        // ---- L0 h-GEMM (B from smem) ----
        #pragma unroll
        for (int j = 0; j < 8; j++) {
            int kk = warp * 8 + j;
            #pragma unroll
            for (int nt = 0; nt < 4; nt++) {
                uint2 bb = *(const uint2*)&s_wh0[((kk * 4 + nt) * 32 + lane) * 2];
                mma16816(acc0[nt], ah0[j], bb);
            }
        }
        // store L0 partials (rows 0-7) -> acc0 dead
        {
            float* rp = s_red + warp * RED_STRIDE;
            #pragma unroll
            for (int nt = 0; nt < 4; nt++) {
                int c0 = (tq * 2) * 4 + nt;
                int c1 = (tq * 2 + 1) * 4 + nt;
                rp[g * 36 + c0]       = acc0[nt][0];
                rp[g * 36 + c1]       = acc0[nt][1];
                rp[(g + 8) * 36 + c0] = acc0[nt][2];
                rp[(g + 8) * 36 + c1] = acc0[nt][3];
            }
        }

        // ---- ah1 loads issued; latency covered by L1in GEMM ----
        uint4 ah1[8];
        {
            const uint4* h1p = (const uint4*)(g_h1f + (size_t)(s & 1) * HFRAG_SZ);
            #pragma unroll
            for (int j = 0; j < 8; j++)
                ah1[j] = ldcg4(h1p + ((warp * 8 + j) * 32 + lane));
        }

        float acc1[4][4];
        #pragma unroll
        for (int nt = 0; nt < 4; nt++)
            #pragma unroll
            for (int j = 0; j < 4; j++) acc1[nt][j] = 0.f;
        // L1 input GEMM: A = ah0 (h0[s-1]), B in regs
        #pragma unroll
        for (int j = 0; j < 8; j++) {
            #pragma unroll
            for (int nt = 0; nt < 4; nt++) mma16816(acc1[nt], ah0[j], bi1r[j][nt]);
        }
        // L1 recurrent GEMM: A = ah1 (h1[s-2])
        #pragma unroll
        for (int j = 0; j < 8; j++) {
            #pragma unroll
            for (int nt = 0; nt < 4; nt++) mma16816(acc1[nt], ah1[j], bh1r[j][nt]);
        }
        // store L1 partials (rows 8-15)
        {
            float* rp = s_red + (8 + warp) * RED_STRIDE;
            #pragma unroll
            for (int nt = 0; nt < 4; nt++) {
                int c0 = (tq * 2) * 4 + nt;
                int c1 = (tq * 2 + 1) * 4 + nt;
                rp[g * 36 + c0]       = acc1[nt][0];
                rp[g * 36 + c1]       = acc1[nt][1];
                rp[(g + 8) * 36 + c0] = acc1[nt][2];
                rp[(g + 8) * 36 + c1] = acc1[nt][3];
            }
        }
        __syncthreads();                       // all s_x reads + red done

        // ---- stage x[s+1] (single buffer safe now); overlaps cell phase ----
        if (s + 1 < T_) {
            const uint4* xs = (const uint4*)(g_xfrag0 + (size_t)(s + 1) * XFRAG_T);
            #pragma unroll
            for (int i = 0; i < 8; i++) cpa16(A_X + (tid + i*NTHR)*16u, xs + tid + i*NTHR);
        }
        CP_COMMIT;

        // ---- cells: warps 0-3 -> L0 step s, warps 4-7 -> L1 step s-1 ----
        float hv = 0.f;
        const bool active = cl ? (s >= 1) : (s < T_);
        if (active) {
            float gi = bs0, gf = bs1, gg = bs2, go = bs3;
            const float* rb = s_red + (cl * 8) * RED_STRIDE + b * 36 + lu * 4;
            #pragma unroll
            for (int w = 0; w < 8; w++) {
                float4 v = *(const float4*)&rb[w * RED_STRIDE];
                gi += v.x;
                gf += v.y;
                gg += v.z;
                go += v.w;
            }
            float fi = sigmoid_ap(gi);
            float ff = sigmoid_ap(gf);
            float fg = tanh_ap(gg);
            float fo = sigmoid_ap(go);
            cc = ff * cc + fi * fg;
            hv = fo * tanh_ap(cc);

            unsigned us = (unsigned)__half_as_ushort(__float2half_rn(hv));
            unsigned other = __shfl_xor_sync(0xffffffffu, us, 16);
            if (lane < 16) {                   // pack (even u | odd u)
                uint32_t packed = us | (other << 16);
                uint32_t* dst = cl ? g_h1f : g_h0f;
                dst[(size_t)((s + 1) & 1) * HFRAG_SZ + h_a32] = packed;
            }
        }

        // ---- early publish: all 8 cell warps' h stores, then one release ----
        asm volatile("bar.sync 1, 256;" ::: "memory");
        if (tid == 0)
            st_release_u32(&g_flags[cblk * FLAG_STRIDE], (unsigned)(s + 1));

        // ---- off-critical-path stores ----
        if (active) {
            if (cl)
                out[((size_t)(s - 1) * B_ + b) * H_ + u] = hv;
            if (nh && s == (cl ? T_ : T_ - 1)) {
                nh[cl * B_ * H_ + b * H_ + u] = hv;
                nc[cl * B_ * H_ + b * H_ + u] = cc;
            }
        }
        CP_WAIT0;                              // x[s+1] staged
        __syncthreads();                       // no run-ahead
    }
}

// ---------------------------------------------------------------------------
extern "C" void kernel_launch(void* const* d_in, const int* in_sizes, int n_in,
                              void* d_out, int out_size) {
    const float* x    = (const float*)d_in[0];
    const float* Wih0 = (const float*)d_in[1];
    const float* bih0 = (const float*)d_in[2];
    const float* Whh0 = (const float*)d_in[3];
    const float* bhh0 = (const float*)d_in[4];
    const float* Wih1 = (const float*)d_in[5];
    const float* bih1 = (const float*)d_in[6];
    const float* Whh1 = (const float*)d_in[7];
    const float* bhh1 = (const float*)d_in[8];
    float* out = (float*)d_out;

    float* nh = nullptr;
    float* nc = nullptr;
    const size_t out1_sz = (size_t)T_ * B_ * H_;
    if ((size_t)out_size >= out1_sz + 4 * B_ * H_) {
        nh = out + out1_sz;
        nc = nh + 2 * B_ * H_;
    }

    static bool attr_done = false;
    if (!attr_done) {
        cudaFuncSetAttribute(k_lstm,
                             cudaFuncAttributeMaxDynamicSharedMemorySize, SMEM_BYTES);
        attr_done = true;
    }

    dim3 gw(2048, 2);
    k_conv_w<<<gw, 256>>>(Wih0, Whh0, Wih1, Whh1);
    k_conv_x<<<4096, 256>>>(x);
    k_reset<<<128, 256>>>();
    k_lstm<<<NCTA, NTHR, SMEM_BYTES>>>(bih0, bhh0, bih1, bhh1, out, nh, nc);
}